// round 12
// baseline (speedup 1.0000x reference)
#include <cuda_runtime.h>
#include <cuda_bf16.h>
#include <math.h>
#include <stdint.h>

#define T_STEPS 1024
#define BATCH   64
#define INDIM   512
#define HID     1024
#define G4      4096

#define NBLK 128
#define THREADS_R 512

// W-resident smem geometry (proven R6-R11)
#define WROWB   2064                 // 1032 bf16 per W row (1024 + 8 pad)
#define WPLANE  (32 * WROWB)         // 66048
#define SM_W    0
#define SM_STAGE (2 * WPLANE)        // 132096
#define SM_RED  (SM_STAGE + 2048)    // 134144 ; 56KB partial-sum exchange
#define R_SMEM  (SM_RED + 57344)     // 191488

// ---------------- device scratch (static) ----------------
__device__ float          g_xproj[(size_t)T_STEPS * BATCH * G4];   // [t][b][j*4+gate]
__device__ __nv_bfloat16  g_xhi[(size_t)T_STEPS * BATCH * INDIM];
__device__ __nv_bfloat16  g_xlo[(size_t)T_STEPS * BATCH * INDIM];
__device__ __nv_bfloat16  g_wihhi[(size_t)G4 * INDIM];
__device__ __nv_bfloat16  g_wihlo[(size_t)G4 * INDIM];
// h packed in m16n8k16 A-fragment order: [buf][plane hi/lo][rb=b>>4][kg=k>>4][lane] = uint4
__device__ uint4          g_hpk[2][2][4][64][32];
__device__ int            g_flags[NBLK];

// ---------------- helpers ----------------
__device__ __forceinline__ uint32_t smem_u32(const void* p) {
    uint32_t a;
    asm("{ .reg .u64 t; cvta.to.shared.u64 t, %1; cvt.u32.u64 %0, t; }" : "=r"(a) : "l"(p));
    return a;
}

#define LDSM_X4(r0,r1,r2,r3,addr) \
    asm volatile("ldmatrix.sync.aligned.m8n8.x4.shared.b16 {%0,%1,%2,%3}, [%4];" \
                 : "=r"(r0), "=r"(r1), "=r"(r2), "=r"(r3) : "r"(addr))

__device__ __forceinline__ void mma_bf16(float& d0, float& d1, float& d2, float& d3,
                                         uint32_t a0, uint32_t a1, uint32_t a2, uint32_t a3,
                                         uint32_t b0, uint32_t b1) {
    asm volatile(
        "mma.sync.aligned.m16n8k16.row.col.f32.bf16.bf16.f32 "
        "{%0,%1,%2,%3}, {%4,%5,%6,%7}, {%8,%9}, {%0,%1,%2,%3};"
        : "+f"(d0), "+f"(d1), "+f"(d2), "+f"(d3)
        : "r"(a0), "r"(a1), "r"(a2), "r"(a3), "r"(b0), "r"(b1));
}

__device__ __forceinline__ void cp16(uint32_t dst, const void* src) {
    asm volatile("cp.async.cg.shared.global [%0], [%1], 16;" :: "r"(dst), "l"(src) : "memory");
}
#define CP_COMMIT() asm volatile("cp.async.commit_group;" ::: "memory")
#define CP_WAIT(n)  asm volatile("cp.async.wait_group %0;" :: "n"(n) : "memory")

// release/acquire flag ops (no MEMBAR.ALL, no CCTL.IVALL L1 flush)
__device__ __forceinline__ void st_rel(int* p, int v) {
    asm volatile("st.release.gpu.global.s32 [%0], %1;" :: "l"(p), "r"(v) : "memory");
}
__device__ __forceinline__ int ld_acq(const int* p) {
    int v;
    asm volatile("ld.acquire.gpu.global.s32 %0, [%1];" : "=r"(v) : "l"(p) : "memory");
    return v;
}

__device__ __forceinline__ void split4(float4 v, uint2& hip, uint2& lop) {
    __nv_bfloat16 hx = __float2bfloat16_rn(v.x);
    __nv_bfloat16 hy = __float2bfloat16_rn(v.y);
    __nv_bfloat16 hz = __float2bfloat16_rn(v.z);
    __nv_bfloat16 hw = __float2bfloat16_rn(v.w);
    __nv_bfloat162 p0 = __halves2bfloat162(hx, hy);
    __nv_bfloat162 p1 = __halves2bfloat162(hz, hw);
    hip.x = *reinterpret_cast<unsigned*>(&p0);
    hip.y = *reinterpret_cast<unsigned*>(&p1);
    __nv_bfloat162 q0 = __floats2bfloat162_rn(v.x - __bfloat162float(hx),
                                              v.y - __bfloat162float(hy));
    __nv_bfloat162 q1 = __floats2bfloat162_rn(v.z - __bfloat162float(hz),
                                              v.w - __bfloat162float(hw));
    lop.x = *reinterpret_cast<unsigned*>(&q0);
    lop.y = *reinterpret_cast<unsigned*>(&q1);
}

__device__ __forceinline__ float sigf(float x) {
    return __fdividef(1.0f, 1.0f + __expf(-x));
}
__device__ __forceinline__ float tanhfast(float x) {
    return __fdividef(2.0f, 1.0f + __expf(-2.0f * x)) - 1.0f;
}

// ================= split pass =================
__global__ __launch_bounds__(256) void split_inputs(
    const float* __restrict__ x,
    const float* __restrict__ wih,
    const float* __restrict__ h0)
{
    if (blockIdx.x == 0 && threadIdx.x < NBLK) g_flags[threadIdx.x] = 0;

    const size_t NX  = (size_t)T_STEPS * BATCH * INDIM / 4;
    const size_t NW  = (size_t)G4 * INDIM / 4;
    const size_t NH0 = (size_t)BATCH * HID / 4;
    const size_t total = NX + NW + NH0;
    for (size_t i = (size_t)blockIdx.x * blockDim.x + threadIdx.x;
         i < total; i += (size_t)gridDim.x * blockDim.x) {
        if (i < NX) {
            float4 v = ((const float4*)x)[i];
            uint2 h, l; split4(v, h, l);
            ((uint2*)g_xhi)[i] = h;
            ((uint2*)g_xlo)[i] = l;
        } else if (i < NX + NW) {
            size_t k = i - NX;
            float4 v = ((const float4*)wih)[k];
            uint2 h, l; split4(v, h, l);
            ((uint2*)g_wihhi)[k] = h;
            ((uint2*)g_wihlo)[k] = l;
        } else {
            size_t e4 = i - NX - NW;
            size_t e  = e4 * 4;
            int b = (int)(e >> 10);
            int kbase = (int)(e & 1023);
            float4 v = ((const float4*)h0)[e4];
            float vv[4] = {v.x, v.y, v.z, v.w};
            int r  = b & 15;
            int rb = b >> 4;
#pragma unroll
            for (int q = 0; q < 4; q++) {
                int k  = kbase + q;
                int kg = k >> 4, kk = k & 15;
                int lanep = ((r & 7) << 2) + ((kk & 7) >> 1);
                int reg   = ((kk >= 8) ? 2 : 0) + ((r >= 8) ? 1 : 0);
                int byte_ = kk & 1;
                __nv_bfloat16 hi = __float2bfloat16_rn(vv[q]);
                __nv_bfloat16 lo = __float2bfloat16_rn(vv[q] - __bfloat162float(hi));
                ((__nv_bfloat16*)&g_hpk[0][0][rb][kg][lanep])[reg * 2 + byte_] = hi;
                ((__nv_bfloat16*)&g_hpk[0][1][rb][kg][lanep])[reg * 2 + byte_] = lo;
            }
        }
    }
}

// ================= x_proj GEMM (chain-separated bf16-split HMMA, R11) =================
#define XP_ROWB 144
#define XP_TILE (128 * XP_ROWB)
#define XP_BUF  (4 * XP_TILE)
#define XP_SMEM (2 * XP_BUF)

__global__ __launch_bounds__(256) void xproj_mma(
    const float* __restrict__ bih,
    const float* __restrict__ bhh)
{
    extern __shared__ char smem[];
    const uint32_t sb = smem_u32(smem);
    const int tid  = threadIdx.x;
    const int lane = tid & 31;
    const int w    = tid >> 5;
    const int wm   = w & 1;
    const int wn   = w >> 1;
    const int jb   = blockIdx.x * 32;
    const size_t mb = (size_t)blockIdx.y * 128;

    float acc[4][4][4];
#pragma unroll
    for (int a = 0; a < 4; a++)
#pragma unroll
        for (int b = 0; b < 4; b++)
#pragma unroll
            for (int c = 0; c < 4; c++) acc[a][b][c] = 0.f;

    const int a_row = wm * 64 + (lane & 7) + ((lane >> 3) & 1) * 8;
    const int a_k8  = (lane >> 4) * 8;
    const int b_row = wn * 32 + (lane & 7) + (lane >> 4) * 8;
    const int b_k8  = ((lane >> 3) & 1) * 8;

    int st_row[4], st_c[4], st_wrow[4];
#pragma unroll
    for (int q = 0; q < 4; q++) {
        int s = tid * 4 + q;
        st_row[q]  = s >> 3;
        st_c[q]    = s & 7;
        st_wrow[q] = (st_row[q] & 3) * HID + jb + (st_row[q] >> 2);
    }

    auto stage = [&](int kb, int buf) {
        uint32_t base = sb + buf * XP_BUF;
#pragma unroll
        for (int q = 0; q < 4; q++) {
            size_t gk = (size_t)kb * 64 + st_c[q] * 8;
            uint32_t off = st_row[q] * XP_ROWB + st_c[q] * 16;
            cp16(base + 0 * XP_TILE + off, &g_xhi[(mb + st_row[q]) * INDIM + gk]);
            cp16(base + 1 * XP_TILE + off, &g_xlo[(mb + st_row[q]) * INDIM + gk]);
            cp16(base + 2 * XP_TILE + off, &g_wihhi[(size_t)st_wrow[q] * INDIM + gk]);
            cp16(base + 3 * XP_TILE + off, &g_wihlo[(size_t)st_wrow[q] * INDIM + gk]);
        }
        CP_COMMIT();
    };

    stage(0, 0);

    for (int kb = 0; kb < 8; kb++) {
        const int buf = kb & 1;
        if (kb < 7) stage(kb + 1, buf ^ 1);
        if (kb < 7) { CP_WAIT(1); } else { CP_WAIT(0); }
        __syncthreads();

        const uint32_t aHi = sb + buf * XP_BUF;
        const uint32_t aLo = aHi + XP_TILE;
        const uint32_t bHi = aHi + 2 * XP_TILE;
        const uint32_t bLo = aHi + 3 * XP_TILE;

#pragma unroll
        for (int s = 0; s < 4; s++) {
            uint32_t bh[8], bl[8];
#pragma unroll
            for (int p = 0; p < 2; p++) {
                uint32_t off = (b_row + p * 16) * XP_ROWB + (s * 16 + b_k8) * 2;
                LDSM_X4(bh[p*4+0], bh[p*4+1], bh[p*4+2], bh[p*4+3], bHi + off);
                LDSM_X4(bl[p*4+0], bl[p*4+1], bl[p*4+2], bl[p*4+3], bLo + off);
            }
#pragma unroll
            for (int mp = 0; mp < 2; mp++) {
                uint32_t ah[2][4], al[2][4];
#pragma unroll
                for (int mi = 0; mi < 2; mi++) {
                    int mt = mp * 2 + mi;
                    uint32_t off = (a_row + mt * 16) * XP_ROWB + (s * 16 + a_k8) * 2;
                    LDSM_X4(ah[mi][0], ah[mi][1], ah[mi][2], ah[mi][3], aHi + off);
                    LDSM_X4(al[mi][0], al[mi][1], al[mi][2], al[mi][3], aLo + off);
                }
#pragma unroll
                for (int mi = 0; mi < 2; mi++)
#pragma unroll
                    for (int nt = 0; nt < 4; nt++) {
                        float* d = acc[mp * 2 + mi][nt];
                        mma_bf16(d[0], d[1], d[2], d[3],
                                 ah[mi][0], ah[mi][1], ah[mi][2], ah[mi][3],
                                 bh[nt*2], bh[nt*2+1]);
                    }
#pragma unroll
                for (int mi = 0; mi < 2; mi++)
#pragma unroll
                    for (int nt = 0; nt < 4; nt++) {
                        float* d = acc[mp * 2 + mi][nt];
                        mma_bf16(d[0], d[1], d[2], d[3],
                                 ah[mi][0], ah[mi][1], ah[mi][2], ah[mi][3],
                                 bl[nt*2], bl[nt*2+1]);
                    }
#pragma unroll
                for (int mi = 0; mi < 2; mi++)
#pragma unroll
                    for (int nt = 0; nt < 4; nt++) {
                        float* d = acc[mp * 2 + mi][nt];
                        mma_bf16(d[0], d[1], d[2], d[3],
                                 al[mi][0], al[mi][1], al[mi][2], al[mi][3],
                                 bh[nt*2], bh[nt*2+1]);
                    }
            }
        }
        __syncthreads();
    }

    const int colq = (lane & 3) * 2;
#pragma unroll
    for (int nt = 0; nt < 4; nt++) {
        int nloc = wn * 32 + nt * 8 + colq;
        int g0 = nloc & 3,        j0 = jb + (nloc >> 2);
        int g1 = (nloc + 1) & 3,  j1 = jb + ((nloc + 1) >> 2);
        float bb0 = bih[g0 * HID + j0] + bhh[g0 * HID + j0];
        float bb1 = bih[g1 * HID + j1] + bhh[g1 * HID + j1];
#pragma unroll
        for (int mt = 0; mt < 4; mt++) {
            size_t r0 = mb + wm * 64 + mt * 16 + (lane >> 2);
            float2 v0 = make_float2(acc[mt][nt][0] + bb0, acc[mt][nt][1] + bb1);
            float2 v1 = make_float2(acc[mt][nt][2] + bb0, acc[mt][nt][3] + bb1);
            *(float2*)&g_xproj[r0 * G4 + jb * 4 + nloc]       = v0;
            *(float2*)&g_xproj[(r0 + 8) * G4 + jb * 4 + nloc] = v1;
        }
    }
}

// ================= persistent recurrent kernel (512 threads, M2xK8) =================
// Warp (mtp, ks in 0..7): m-tiles {2mtp, 2mtp+1}, all 32 N-cols, kg in [8ks, 8ks+8).
// A loads disjoint (__ldcg). 8-way K reduction via smem. Cell warps: ks<2, mt=2mtp+ks.
__global__ __launch_bounds__(THREADS_R, 1) void lstm_rec_pk(
    const float* __restrict__ c0in,
    const float* __restrict__ whh,
    float* __restrict__ out, int out_size)
{
    extern __shared__ char smem[];
    const uint32_t sb = smem_u32(smem);
    const int tid  = threadIdx.x;
    const int lane = tid & 31;
    const int w    = tid >> 5;
    const int mtp  = w & 1;            // m pair
    const int ks   = w >> 1;           // K eighth (0..7)
    const int blk  = blockIdx.x;
    const int hb   = blk * 8;
    const int kgc  = blk >> 1;

    // one-time: W slice -> smem (gate-interleaved rows, proven mapping), hi+lo
    for (int it = 0; it < 16; it++) {
        int e4 = it * THREADS_R + tid;
        int n  = e4 >> 8;
        int kf = (e4 & 255) * 4;
        int nh_ = n >> 4, r = n & 15;
        int nt = r >> 3, q = (r & 7) >> 1, low = r & 1;
        int gate = nt * 2 + low, j = 4 * nh_ + q;
        float4 v = *(const float4*)&whh[(size_t)(gate * HID + hb + j) * HID + kf];
        uint2 hp, lp; split4(v, hp, lp);
        *(uint2*)(smem + SM_W + n * WROWB + kf * 2) = hp;
        *(uint2*)(smem + SM_W + WPLANE + n * WROWB + kf * 2) = lp;
    }
    __syncthreads();

    const uint32_t bRow0 = (uint32_t)((lane & 7) + ((lane >> 4) << 3)) * WROWB;
    const uint32_t bRow1 = bRow0 + 16u * WROWB;
    const uint32_t bK8   = ((lane >> 3) & 1) * 8;

    const int j0 = lane & 3;
    const int j1 = 4 + j0;
    const int col0 = hb + j0;
    const int col1 = hb + j1;

    // cell role: warps ks<2 handle mt = 2*mtp + ks
    const int cmt = 2 * mtp + ks;                 // valid when ks<2
    const int cb0 = cmt * 16 + (lane >> 2);
    const int cb1 = cb0 + 8;
    const uint32_t off0 = (uint32_t)(cmt * 32 + ((lane >> 2) << 2) + (j0 >> 1)) * 8 + (j0 & 1) * 2;
    const uint32_t off1 = (uint32_t)(cmt * 32 + ((lane >> 2) << 2) + (j1 >> 1)) * 8 + (j1 & 1) * 2;

    float cst[4] = {0.f, 0.f, 0.f, 0.f};
    float4 xg0, xg1, xg2, xg3;
    if (ks < 2) {
        cst[0] = c0in[cb0 * HID + col0];
        cst[1] = c0in[cb1 * HID + col0];
        cst[2] = c0in[cb0 * HID + col1];
        cst[3] = c0in[cb1 * HID + col1];
        const float* xpb = g_xproj;
        xg0 = *(const float4*)(xpb + (size_t)cb0 * G4 + col0 * 4);
        xg1 = *(const float4*)(xpb + (size_t)cb1 * G4 + col0 * 4);
        xg2 = *(const float4*)(xpb + (size_t)cb0 * G4 + col1 * 4);
        xg3 = *(const float4*)(xpb + (size_t)cb1 * G4 + col1 * 4);
    }

    // red layout: [mtp(2)][mti(2)][src(7)][tt(4)][lane(32)] float4
    float4* red = (float4*)(smem + SM_RED);

    for (int t = 0; t < T_STEPS; t++) {
        const int rbuf = t & 1;
        const uint4* __restrict__ Ahp[2];
        const uint4* __restrict__ Alp[2];
#pragma unroll
        for (int mti = 0; mti < 2; mti++) {
            Ahp[mti] = &g_hpk[rbuf][0][2 * mtp + mti][ks * 8][lane];
            Alp[mti] = &g_hpk[rbuf][1][2 * mtp + mti][ks * 8][lane];
        }

        // 3-deep A prefetch per m-tile
        uint4 pah[3][2], pal[3][2];
#pragma unroll
        for (int i = 0; i < 3; i++)
#pragma unroll
            for (int mti = 0; mti < 2; mti++) {
                pah[i][mti] = __ldcg(&Ahp[mti][i * 32]);
                pal[i][mti] = __ldcg(&Alp[mti][i * 32]);
            }

        float G[2][4][4];
#pragma unroll
        for (int mti = 0; mti < 2; mti++)
#pragma unroll
            for (int tt = 0; tt < 4; tt++)
#pragma unroll
                for (int c = 0; c < 4; c++) G[mti][tt][c] = 0.f;

#pragma unroll
        for (int kg = 0; kg < 8; kg++) {
            const int slot = kg % 3;
            uint4 vh[2], vl[2];
#pragma unroll
            for (int mti = 0; mti < 2; mti++) { vh[mti] = pah[slot][mti]; vl[mti] = pal[slot][mti]; }
            if (kg + 3 < 8) {
#pragma unroll
                for (int mti = 0; mti < 2; mti++) {
                    pah[slot][mti] = __ldcg(&Ahp[mti][(kg + 3) * 32]);
                    pal[slot][mti] = __ldcg(&Alp[mti][(kg + 3) * 32]);
                }
            }
            const int kgg = ks * 8 + kg;
            const uint32_t ko = (uint32_t)((kgg * 16 + bK8) << 1);
            uint32_t bh[8], bl[8];
            LDSM_X4(bh[0], bh[1], bh[2], bh[3], sb + SM_W + bRow0 + ko);
            LDSM_X4(bh[4], bh[5], bh[6], bh[7], sb + SM_W + bRow1 + ko);
            LDSM_X4(bl[0], bl[1], bl[2], bl[3], sb + SM_W + WPLANE + bRow0 + ko);
            LDSM_X4(bl[4], bl[5], bl[6], bl[7], sb + SM_W + WPLANE + bRow1 + ko);
            // pass 1: hi * Whi
#pragma unroll
            for (int mti = 0; mti < 2; mti++)
#pragma unroll
                for (int tt = 0; tt < 4; tt++)
                    mma_bf16(G[mti][tt][0], G[mti][tt][1], G[mti][tt][2], G[mti][tt][3],
                             vh[mti].x, vh[mti].y, vh[mti].z, vh[mti].w, bh[tt*2], bh[tt*2+1]);
            // pass 2: hi * Wlo
#pragma unroll
            for (int mti = 0; mti < 2; mti++)
#pragma unroll
                for (int tt = 0; tt < 4; tt++)
                    mma_bf16(G[mti][tt][0], G[mti][tt][1], G[mti][tt][2], G[mti][tt][3],
                             vh[mti].x, vh[mti].y, vh[mti].z, vh[mti].w, bl[tt*2], bl[tt*2+1]);
            // pass 3: lo * Whi
#pragma unroll
            for (int mti = 0; mti < 2; mti++)
#pragma unroll
                for (int tt = 0; tt < 4; tt++)
                    mma_bf16(G[mti][tt][0], G[mti][tt][1], G[mti][tt][2], G[mti][tt][3],
                             vl[mti].x, vl[mti].y, vl[mti].z, vl[mti].w, bh[tt*2], bh[tt*2+1]);
        }

        // write partials for (mtp,mti) unless this warp is its cell warp (ks==mti)
        {
#pragma unroll
            for (int mti = 0; mti < 2; mti++) {
                if (ks != mti) {
                    int src = ks - (ks > mti ? 1 : 0);   // 0..6
                    int base = (((mtp * 2 + mti) * 7) + src) * 4;
#pragma unroll
                    for (int tt = 0; tt < 4; tt++)
                        red[(base + tt) * 32 + lane] =
                            make_float4(G[mti][tt][0], G[mti][tt][1],
                                        G[mti][tt][2], G[mti][tt][3]);
                }
            }
        }
        __syncthreads();

        float hvv[4];
        if (ks < 2) {
            const int mti = ks;
#pragma unroll
            for (int src = 0; src < 7; src++) {
                int base = (((mtp * 2 + mti) * 7) + src) * 4;
#pragma unroll
                for (int tt = 0; tt < 4; tt++) {
                    float4 v = red[(base + tt) * 32 + lane];
                    G[mti][tt][0] += v.x; G[mti][tt][1] += v.y;
                    G[mti][tt][2] += v.z; G[mti][tt][3] += v.w;
                }
            }
            float (*Gm)[4] = G[mti];
            float ig, fg, gg, og;
            ig = sigf(Gm[0][0] + xg0.x); fg = sigf(Gm[0][1] + xg0.y);
            gg = tanhfast(Gm[1][0] + xg0.z); og = sigf(Gm[1][1] + xg0.w);
            cst[0] = fg * cst[0] + ig * gg;  hvv[0] = og * tanhfast(cst[0]);

            ig = sigf(Gm[0][2] + xg1.x); fg = sigf(Gm[0][3] + xg1.y);
            gg = tanhfast(Gm[1][2] + xg1.z); og = sigf(Gm[1][3] + xg1.w);
            cst[1] = fg * cst[1] + ig * gg;  hvv[1] = og * tanhfast(cst[1]);

            ig = sigf(Gm[2][0] + xg2.x); fg = sigf(Gm[2][1] + xg2.y);
            gg = tanhfast(Gm[3][0] + xg2.z); og = sigf(Gm[3][1] + xg2.w);
            cst[2] = fg * cst[2] + ig * gg;  hvv[2] = og * tanhfast(cst[2]);

            ig = sigf(Gm[2][2] + xg3.x); fg = sigf(Gm[2][3] + xg3.y);
            gg = tanhfast(Gm[3][2] + xg3.z); og = sigf(Gm[3][3] + xg3.w);
            cst[3] = fg * cst[3] + ig * gg;  hvv[3] = og * tanhfast(cst[3]);

            // stage packed-h slice
            char* st = smem + SM_STAGE;
            __nv_bfloat16 h0 = __float2bfloat16_rn(hvv[0]);
            __nv_bfloat16 h1 = __float2bfloat16_rn(hvv[1]);
            __nv_bfloat16 h2 = __float2bfloat16_rn(hvv[2]);
            __nv_bfloat16 h3 = __float2bfloat16_rn(hvv[3]);
            *(__nv_bfloat16*)(st + off0)        = h0;
            *(__nv_bfloat16*)(st + off0 + 4)    = h1;
            *(__nv_bfloat16*)(st + off1)        = h2;
            *(__nv_bfloat16*)(st + off1 + 4)    = h3;
            *(__nv_bfloat16*)(st + off0 + 1024) = __float2bfloat16_rn(hvv[0] - __bfloat162float(h0));
            *(__nv_bfloat16*)(st + off0 + 1028) = __float2bfloat16_rn(hvv[1] - __bfloat162float(h1));
            *(__nv_bfloat16*)(st + off1 + 1024) = __float2bfloat16_rn(hvv[2] - __bfloat162float(h2));
            *(__nv_bfloat16*)(st + off1 + 1028) = __float2bfloat16_rn(hvv[3] - __bfloat162float(h3));
        }
        __syncthreads();

        // coalesced packed writeback: first 256 threads, one STG.64 each
        if (tid < 256) {
            const int wbuf = (t + 1) & 1;
            int plane = tid >> 7, rb = (tid >> 5) & 3, lt = tid & 31;
            uint2 v = *(uint2*)(smem + SM_STAGE + (uint32_t)((plane * 4 + rb) * 32 + lt) * 8);
            uint2* dst = (uint2*)&g_hpk[wbuf][plane][rb][kgc][lt];
            dst[blk & 1] = v;
        }

        if (t == T_STEPS - 1) {
            if (ks < 2) {
                out[((size_t)t * BATCH + cb0) * HID + col0] = hvv[0];
                out[((size_t)t * BATCH + cb1) * HID + col0] = hvv[1];
                out[((size_t)t * BATCH + cb0) * HID + col1] = hvv[2];
                out[((size_t)t * BATCH + cb1) * HID + col1] = hvv[3];
                const long long need = (long long)T_STEPS * BATCH * HID + 2LL * BATCH * HID;
                if ((long long)out_size >= need) {
                    size_t base = (size_t)T_STEPS * BATCH * HID;
                    out[base + (size_t)cb0 * HID + col0] = hvv[0];
                    out[base + (size_t)cb1 * HID + col0] = hvv[1];
                    out[base + (size_t)cb0 * HID + col1] = hvv[2];
                    out[base + (size_t)cb1 * HID + col1] = hvv[3];
                    size_t cb = base + (size_t)BATCH * HID;
                    out[cb + (size_t)cb0 * HID + col0] = cst[0];
                    out[cb + (size_t)cb1 * HID + col0] = cst[1];
                    out[cb + (size_t)cb0 * HID + col1] = cst[2];
                    out[cb + (size_t)cb1 * HID + col1] = cst[3];
                }
            }
        } else {
            // writeback STGs -> bar -> release flag; all threads acquire-poll.
            __syncthreads();
            if (tid == 0) st_rel(&g_flags[blk], t + 1);
            if (ks < 2) {
                // out stores + next-step xg prefetch off the critical path
                out[((size_t)t * BATCH + cb0) * HID + col0] = hvv[0];
                out[((size_t)t * BATCH + cb1) * HID + col0] = hvv[1];
                out[((size_t)t * BATCH + cb0) * HID + col1] = hvv[2];
                out[((size_t)t * BATCH + cb1) * HID + col1] = hvv[3];
                const float* xpb = g_xproj + ((size_t)(t + 1) * BATCH) * G4;
                xg0 = *(const float4*)(xpb + (size_t)cb0 * G4 + col0 * 4);
                xg1 = *(const float4*)(xpb + (size_t)cb1 * G4 + col0 * 4);
                xg2 = *(const float4*)(xpb + (size_t)cb0 * G4 + col1 * 4);
                xg3 = *(const float4*)(xpb + (size_t)cb1 * G4 + col1 * 4);
            }
            // all threads poll (covers all 128 flags; replaces trailing bar)
            while (ld_acq(&g_flags[tid & 127]) < t + 1) { }
        }
    }
}

// ================= launch =================
extern "C" void kernel_launch(void* const* d_in, const int* in_sizes, int n_in,
                              void* d_out, int out_size) {
    const float* x    = (const float*)d_in[0];
    const float* h0   = (const float*)d_in[1];
    const float* c0   = (const float*)d_in[2];
    const float* w_ih = (const float*)d_in[3];
    const float* w_hh = (const float*)d_in[4];
    const float* b_ih = (const float*)d_in[5];
    const float* b_hh = (const float*)d_in[6];
    float* out = (float*)d_out;

    cudaFuncSetAttribute(xproj_mma,
                         cudaFuncAttributeMaxDynamicSharedMemorySize, XP_SMEM);
    cudaFuncSetAttribute(lstm_rec_pk,
                         cudaFuncAttributeMaxDynamicSharedMemorySize, R_SMEM);

    split_inputs<<<2048, 256>>>(x, w_ih, h0);
    dim3 gx(G4 / 128, (T_STEPS * BATCH) / 128);   // 32 x 512
    xproj_mma<<<gx, 256, XP_SMEM>>>(b_ih, b_hh);
    lstm_rec_pk<<<NBLK, THREADS_R, R_SMEM>>>(c0, w_hh, out, out_size);
}

// round 13
// speedup vs baseline: 1.3495x; 1.3495x over previous
#include <cuda_runtime.h>
#include <cuda_bf16.h>
#include <math.h>
#include <stdint.h>

#define T_STEPS 1024
#define BATCH   64
#define INDIM   512
#define HID     1024
#define G4      4096

#define NBLK 128

// W-resident smem geometry (proven R6-R11)
#define WROWB   2064                 // 1032 bf16 per W row (1024 + 8 pad)
#define WPLANE  (32 * WROWB)         // 66048
#define SM_W    0
#define SM_STAGE (2 * WPLANE)        // 132096
#define SM_RED  (SM_STAGE + 2048)    // 134144 ; 24KB partial-sum exchange
#define R_SMEM  (SM_RED + 24576)     // 158720

// ---------------- device scratch (static) ----------------
__device__ float          g_xproj[(size_t)T_STEPS * BATCH * G4];   // [t][b][j*4+gate]
__device__ __nv_bfloat16  g_xhi[(size_t)T_STEPS * BATCH * INDIM];
__device__ __nv_bfloat16  g_xlo[(size_t)T_STEPS * BATCH * INDIM];
__device__ __nv_bfloat16  g_wihhi[(size_t)G4 * INDIM];
__device__ __nv_bfloat16  g_wihlo[(size_t)G4 * INDIM];
// h packed in m16n8k16 A-fragment order: [buf][plane hi/lo][rb=b>>4][kg=k>>4][lane] = uint4
__device__ uint4          g_hpk[2][2][4][64][32];
__device__ int            g_flags[NBLK];

// ---------------- helpers ----------------
__device__ __forceinline__ uint32_t smem_u32(const void* p) {
    uint32_t a;
    asm("{ .reg .u64 t; cvta.to.shared.u64 t, %1; cvt.u32.u64 %0, t; }" : "=r"(a) : "l"(p));
    return a;
}

#define LDSM_X4(r0,r1,r2,r3,addr) \
    asm volatile("ldmatrix.sync.aligned.m8n8.x4.shared.b16 {%0,%1,%2,%3}, [%4];" \
                 : "=r"(r0), "=r"(r1), "=r"(r2), "=r"(r3) : "r"(addr))

__device__ __forceinline__ void mma_bf16(float& d0, float& d1, float& d2, float& d3,
                                         uint32_t a0, uint32_t a1, uint32_t a2, uint32_t a3,
                                         uint32_t b0, uint32_t b1) {
    asm volatile(
        "mma.sync.aligned.m16n8k16.row.col.f32.bf16.bf16.f32 "
        "{%0,%1,%2,%3}, {%4,%5,%6,%7}, {%8,%9}, {%0,%1,%2,%3};"
        : "+f"(d0), "+f"(d1), "+f"(d2), "+f"(d3)
        : "r"(a0), "r"(a1), "r"(a2), "r"(a3), "r"(b0), "r"(b1));
}

__device__ __forceinline__ void cp16(uint32_t dst, const void* src) {
    asm volatile("cp.async.cg.shared.global [%0], [%1], 16;" :: "r"(dst), "l"(src) : "memory");
}
#define CP_COMMIT() asm volatile("cp.async.commit_group;" ::: "memory")
#define CP_WAIT(n)  asm volatile("cp.async.wait_group %0;" :: "n"(n) : "memory")

// release/acquire flag ops (no MEMBAR.ALL, no CCTL.IVALL L1 flush)
__device__ __forceinline__ void st_rel(int* p, int v) {
    asm volatile("st.release.gpu.global.s32 [%0], %1;" :: "l"(p), "r"(v) : "memory");
}
__device__ __forceinline__ int ld_acq(const int* p) {
    int v;
    asm volatile("ld.acquire.gpu.global.s32 %0, [%1];" : "=r"(v) : "l"(p) : "memory");
    return v;
}

__device__ __forceinline__ void split4(float4 v, uint2& hip, uint2& lop) {
    __nv_bfloat16 hx = __float2bfloat16_rn(v.x);
    __nv_bfloat16 hy = __float2bfloat16_rn(v.y);
    __nv_bfloat16 hz = __float2bfloat16_rn(v.z);
    __nv_bfloat16 hw = __float2bfloat16_rn(v.w);
    __nv_bfloat162 p0 = __halves2bfloat162(hx, hy);
    __nv_bfloat162 p1 = __halves2bfloat162(hz, hw);
    hip.x = *reinterpret_cast<unsigned*>(&p0);
    hip.y = *reinterpret_cast<unsigned*>(&p1);
    __nv_bfloat162 q0 = __floats2bfloat162_rn(v.x - __bfloat162float(hx),
                                              v.y - __bfloat162float(hy));
    __nv_bfloat162 q1 = __floats2bfloat162_rn(v.z - __bfloat162float(hz),
                                              v.w - __bfloat162float(hw));
    lop.x = *reinterpret_cast<unsigned*>(&q0);
    lop.y = *reinterpret_cast<unsigned*>(&q1);
}

__device__ __forceinline__ float sigf(float x) {
    return __fdividef(1.0f, 1.0f + __expf(-x));
}
__device__ __forceinline__ float tanhfast(float x) {
    return __fdividef(2.0f, 1.0f + __expf(-2.0f * x)) - 1.0f;
}

// ================= split pass =================
__global__ __launch_bounds__(256) void split_inputs(
    const float* __restrict__ x,
    const float* __restrict__ wih,
    const float* __restrict__ h0)
{
    if (blockIdx.x == 0 && threadIdx.x < NBLK) g_flags[threadIdx.x] = 0;

    const size_t NX  = (size_t)T_STEPS * BATCH * INDIM / 4;
    const size_t NW  = (size_t)G4 * INDIM / 4;
    const size_t NH0 = (size_t)BATCH * HID / 4;
    const size_t total = NX + NW + NH0;
    for (size_t i = (size_t)blockIdx.x * blockDim.x + threadIdx.x;
         i < total; i += (size_t)gridDim.x * blockDim.x) {
        if (i < NX) {
            float4 v = ((const float4*)x)[i];
            uint2 h, l; split4(v, h, l);
            ((uint2*)g_xhi)[i] = h;
            ((uint2*)g_xlo)[i] = l;
        } else if (i < NX + NW) {
            size_t k = i - NX;
            float4 v = ((const float4*)wih)[k];
            uint2 h, l; split4(v, h, l);
            ((uint2*)g_wihhi)[k] = h;
            ((uint2*)g_wihlo)[k] = l;
        } else {
            size_t e4 = i - NX - NW;
            size_t e  = e4 * 4;
            int b = (int)(e >> 10);
            int kbase = (int)(e & 1023);
            float4 v = ((const float4*)h0)[e4];
            float vv[4] = {v.x, v.y, v.z, v.w};
            int r  = b & 15;
            int rb = b >> 4;
#pragma unroll
            for (int q = 0; q < 4; q++) {
                int k  = kbase + q;
                int kg = k >> 4, kk = k & 15;
                int lanep = ((r & 7) << 2) + ((kk & 7) >> 1);
                int reg   = ((kk >= 8) ? 2 : 0) + ((r >= 8) ? 1 : 0);
                int byte_ = kk & 1;
                __nv_bfloat16 hi = __float2bfloat16_rn(vv[q]);
                __nv_bfloat16 lo = __float2bfloat16_rn(vv[q] - __bfloat162float(hi));
                ((__nv_bfloat16*)&g_hpk[0][0][rb][kg][lanep])[reg * 2 + byte_] = hi;
                ((__nv_bfloat16*)&g_hpk[0][1][rb][kg][lanep])[reg * 2 + byte_] = lo;
            }
        }
    }
}

// ================= x_proj GEMM (chain-separated bf16-split HMMA, R11) =================
#define XP_ROWB 144
#define XP_TILE (128 * XP_ROWB)
#define XP_BUF  (4 * XP_TILE)
#define XP_SMEM (2 * XP_BUF)

__global__ __launch_bounds__(256) void xproj_mma(
    const float* __restrict__ bih,
    const float* __restrict__ bhh)
{
    extern __shared__ char smem[];
    const uint32_t sb = smem_u32(smem);
    const int tid  = threadIdx.x;
    const int lane = tid & 31;
    const int w    = tid >> 5;
    const int wm   = w & 1;
    const int wn   = w >> 1;
    const int jb   = blockIdx.x * 32;
    const size_t mb = (size_t)blockIdx.y * 128;

    float acc[4][4][4];
#pragma unroll
    for (int a = 0; a < 4; a++)
#pragma unroll
        for (int b = 0; b < 4; b++)
#pragma unroll
            for (int c = 0; c < 4; c++) acc[a][b][c] = 0.f;

    const int a_row = wm * 64 + (lane & 7) + ((lane >> 3) & 1) * 8;
    const int a_k8  = (lane >> 4) * 8;
    const int b_row = wn * 32 + (lane & 7) + (lane >> 4) * 8;
    const int b_k8  = ((lane >> 3) & 1) * 8;

    int st_row[4], st_c[4], st_wrow[4];
#pragma unroll
    for (int q = 0; q < 4; q++) {
        int s = tid * 4 + q;
        st_row[q]  = s >> 3;
        st_c[q]    = s & 7;
        st_wrow[q] = (st_row[q] & 3) * HID + jb + (st_row[q] >> 2);
    }

    auto stage = [&](int kb, int buf) {
        uint32_t base = sb + buf * XP_BUF;
#pragma unroll
        for (int q = 0; q < 4; q++) {
            size_t gk = (size_t)kb * 64 + st_c[q] * 8;
            uint32_t off = st_row[q] * XP_ROWB + st_c[q] * 16;
            cp16(base + 0 * XP_TILE + off, &g_xhi[(mb + st_row[q]) * INDIM + gk]);
            cp16(base + 1 * XP_TILE + off, &g_xlo[(mb + st_row[q]) * INDIM + gk]);
            cp16(base + 2 * XP_TILE + off, &g_wihhi[(size_t)st_wrow[q] * INDIM + gk]);
            cp16(base + 3 * XP_TILE + off, &g_wihlo[(size_t)st_wrow[q] * INDIM + gk]);
        }
        CP_COMMIT();
    };

    stage(0, 0);

    for (int kb = 0; kb < 8; kb++) {
        const int buf = kb & 1;
        if (kb < 7) stage(kb + 1, buf ^ 1);
        if (kb < 7) { CP_WAIT(1); } else { CP_WAIT(0); }
        __syncthreads();

        const uint32_t aHi = sb + buf * XP_BUF;
        const uint32_t aLo = aHi + XP_TILE;
        const uint32_t bHi = aHi + 2 * XP_TILE;
        const uint32_t bLo = aHi + 3 * XP_TILE;

#pragma unroll
        for (int s = 0; s < 4; s++) {
            uint32_t bh[8], bl[8];
#pragma unroll
            for (int p = 0; p < 2; p++) {
                uint32_t off = (b_row + p * 16) * XP_ROWB + (s * 16 + b_k8) * 2;
                LDSM_X4(bh[p*4+0], bh[p*4+1], bh[p*4+2], bh[p*4+3], bHi + off);
                LDSM_X4(bl[p*4+0], bl[p*4+1], bl[p*4+2], bl[p*4+3], bLo + off);
            }
#pragma unroll
            for (int mp = 0; mp < 2; mp++) {
                uint32_t ah[2][4], al[2][4];
#pragma unroll
                for (int mi = 0; mi < 2; mi++) {
                    int mt = mp * 2 + mi;
                    uint32_t off = (a_row + mt * 16) * XP_ROWB + (s * 16 + a_k8) * 2;
                    LDSM_X4(ah[mi][0], ah[mi][1], ah[mi][2], ah[mi][3], aHi + off);
                    LDSM_X4(al[mi][0], al[mi][1], al[mi][2], al[mi][3], aLo + off);
                }
#pragma unroll
                for (int mi = 0; mi < 2; mi++)
#pragma unroll
                    for (int nt = 0; nt < 4; nt++) {
                        float* d = acc[mp * 2 + mi][nt];
                        mma_bf16(d[0], d[1], d[2], d[3],
                                 ah[mi][0], ah[mi][1], ah[mi][2], ah[mi][3],
                                 bh[nt*2], bh[nt*2+1]);
                    }
#pragma unroll
                for (int mi = 0; mi < 2; mi++)
#pragma unroll
                    for (int nt = 0; nt < 4; nt++) {
                        float* d = acc[mp * 2 + mi][nt];
                        mma_bf16(d[0], d[1], d[2], d[3],
                                 ah[mi][0], ah[mi][1], ah[mi][2], ah[mi][3],
                                 bl[nt*2], bl[nt*2+1]);
                    }
#pragma unroll
                for (int mi = 0; mi < 2; mi++)
#pragma unroll
                    for (int nt = 0; nt < 4; nt++) {
                        float* d = acc[mp * 2 + mi][nt];
                        mma_bf16(d[0], d[1], d[2], d[3],
                                 al[mi][0], al[mi][1], al[mi][2], al[mi][3],
                                 bh[nt*2], bh[nt*2+1]);
                    }
            }
        }
        __syncthreads();
    }

    const int colq = (lane & 3) * 2;
#pragma unroll
    for (int nt = 0; nt < 4; nt++) {
        int nloc = wn * 32 + nt * 8 + colq;
        int g0 = nloc & 3,        j0 = jb + (nloc >> 2);
        int g1 = (nloc + 1) & 3,  j1 = jb + ((nloc + 1) >> 2);
        float bb0 = bih[g0 * HID + j0] + bhh[g0 * HID + j0];
        float bb1 = bih[g1 * HID + j1] + bhh[g1 * HID + j1];
#pragma unroll
        for (int mt = 0; mt < 4; mt++) {
            size_t r0 = mb + wm * 64 + mt * 16 + (lane >> 2);
            float2 v0 = make_float2(acc[mt][nt][0] + bb0, acc[mt][nt][1] + bb1);
            float2 v1 = make_float2(acc[mt][nt][2] + bb0, acc[mt][nt][3] + bb1);
            *(float2*)&g_xproj[r0 * G4 + jb * 4 + nloc]       = v0;
            *(float2*)&g_xproj[(r0 + 8) * G4 + jb * 4 + nloc] = v1;
        }
    }
}

// ================= persistent recurrent kernel (M2xK4, per-producer waits) =================
// Warp (mtp, ks): m-tiles {2mtp, 2mtp+1}, all 32 N-cols, kg in [16ks, 16ks+16).
// Warp ks depends ONLY on producer CTAs [32ks, 32ks+32): per-warp flag wait at
// MMA head replaces the global barrier (2-buffer safety: a CTA's writeback at
// step t+1 follows all 4 warps' waits = all 128 flags >= t+1, so every CTA has
// finished reading the buffer being overwritten).
__global__ __launch_bounds__(256, 1) void lstm_rec_pk(
    const float* __restrict__ c0in,
    const float* __restrict__ whh,
    float* __restrict__ out, int out_size)
{
    extern __shared__ char smem[];
    const uint32_t sb = smem_u32(smem);
    const int tid  = threadIdx.x;
    const int lane = tid & 31;
    const int w    = tid >> 5;
    const int mtp  = w & 1;            // m pair
    const int ks   = w >> 1;           // K quarter
    const int blk  = blockIdx.x;
    const int hb   = blk * 8;
    const int kgc  = blk >> 1;

    // one-time: W slice -> smem (gate-interleaved rows, proven mapping), hi+lo
    for (int it = 0; it < 32; it++) {
        int e4 = it * 256 + tid;
        int n  = e4 >> 8;
        int kf = (e4 & 255) * 4;
        int nh_ = n >> 4, r = n & 15;
        int nt = r >> 3, q = (r & 7) >> 1, low = r & 1;
        int gate = nt * 2 + low, j = 4 * nh_ + q;
        float4 v = *(const float4*)&whh[(size_t)(gate * HID + hb + j) * HID + kf];
        uint2 hp, lp; split4(v, hp, lp);
        *(uint2*)(smem + SM_W + n * WROWB + kf * 2) = hp;
        *(uint2*)(smem + SM_W + WPLANE + n * WROWB + kf * 2) = lp;
    }
    __syncthreads();

    const uint32_t bRow0 = (uint32_t)((lane & 7) + ((lane >> 4) << 3)) * WROWB;
    const uint32_t bRow1 = bRow0 + 16u * WROWB;
    const uint32_t bK8   = ((lane >> 3) & 1) * 8;

    const int j0 = lane & 3;
    const int j1 = 4 + j0;
    const int col0 = hb + j0;
    const int col1 = hb + j1;

    // cell role: warps ks<2 handle mt = 2*mtp + ks
    const int cmt = 2 * mtp + ks;                 // valid when ks<2
    const int cb0 = cmt * 16 + (lane >> 2);
    const int cb1 = cb0 + 8;
    const uint32_t off0 = (uint32_t)(cmt * 32 + ((lane >> 2) << 2) + (j0 >> 1)) * 8 + (j0 & 1) * 2;
    const uint32_t off1 = (uint32_t)(cmt * 32 + ((lane >> 2) << 2) + (j1 >> 1)) * 8 + (j1 & 1) * 2;

    // this warp's producer flag (one per lane): CTAs [32*ks, 32*ks+32)
    int* my_flag = &g_flags[32 * ks + lane];

    float cst[4] = {0.f, 0.f, 0.f, 0.f};
    float4 xg0, xg1, xg2, xg3;
    if (ks < 2) {
        cst[0] = c0in[cb0 * HID + col0];
        cst[1] = c0in[cb1 * HID + col0];
        cst[2] = c0in[cb0 * HID + col1];
        cst[3] = c0in[cb1 * HID + col1];
        const float* xpb = g_xproj;
        xg0 = *(const float4*)(xpb + (size_t)cb0 * G4 + col0 * 4);
        xg1 = *(const float4*)(xpb + (size_t)cb1 * G4 + col0 * 4);
        xg2 = *(const float4*)(xpb + (size_t)cb0 * G4 + col1 * 4);
        xg3 = *(const float4*)(xpb + (size_t)cb1 * G4 + col1 * 4);
    }

    float4* red = (float4*)(smem + SM_RED);   // [src(3)][mtp(2)][mti(2)][tt(4)][lane]

    for (int t = 0; t < T_STEPS; t++) {
        // per-warp producer wait: h for step t carries flag value t
        if (ld_acq(my_flag) < t) {
            while (ld_acq(my_flag) < t) { __nanosleep(32); }
        }
        __syncwarp();

        const int rbuf = t & 1;
        const uint4* __restrict__ Ahp[2];
        const uint4* __restrict__ Alp[2];
#pragma unroll
        for (int mti = 0; mti < 2; mti++) {
            Ahp[mti] = &g_hpk[rbuf][0][2 * mtp + mti][ks * 16][lane];
            Alp[mti] = &g_hpk[rbuf][1][2 * mtp + mti][ks * 16][lane];
        }

        // 6-deep A prefetch per m-tile (24 outstanding uint4/thread)
        uint4 pah[6][2], pal[6][2];
#pragma unroll
        for (int i = 0; i < 6; i++)
#pragma unroll
            for (int mti = 0; mti < 2; mti++) {
                pah[i][mti] = __ldcg(&Ahp[mti][i * 32]);
                pal[i][mti] = __ldcg(&Alp[mti][i * 32]);
            }

        float am[2][4][4], ac[2][4][4];
#pragma unroll
        for (int mti = 0; mti < 2; mti++)
#pragma unroll
            for (int tt = 0; tt < 4; tt++)
#pragma unroll
                for (int c = 0; c < 4; c++) { am[mti][tt][c] = 0.f; ac[mti][tt][c] = 0.f; }

#pragma unroll
        for (int kg = 0; kg < 16; kg++) {
            const int slot = kg % 6;
            uint4 vh[2], vl[2];
#pragma unroll
            for (int mti = 0; mti < 2; mti++) { vh[mti] = pah[slot][mti]; vl[mti] = pal[slot][mti]; }
            if (kg + 6 < 16) {
#pragma unroll
                for (int mti = 0; mti < 2; mti++) {
                    pah[slot][mti] = __ldcg(&Ahp[mti][(kg + 6) * 32]);
                    pal[slot][mti] = __ldcg(&Alp[mti][(kg + 6) * 32]);
                }
            }
            const int kgg = ks * 16 + kg;
            const uint32_t ko = (uint32_t)((kgg * 16 + bK8) << 1);
            uint32_t bh[8], bl[8];
            LDSM_X4(bh[0], bh[1], bh[2], bh[3], sb + SM_W + bRow0 + ko);
            LDSM_X4(bh[4], bh[5], bh[6], bh[7], sb + SM_W + bRow1 + ko);
            LDSM_X4(bl[0], bl[1], bl[2], bl[3], sb + SM_W + WPLANE + bRow0 + ko);
            LDSM_X4(bl[4], bl[5], bl[6], bl[7], sb + SM_W + WPLANE + bRow1 + ko);
            // pass 1: hi * Whi (main chain)
#pragma unroll
            for (int mti = 0; mti < 2; mti++)
#pragma unroll
                for (int tt = 0; tt < 4; tt++)
                    mma_bf16(am[mti][tt][0], am[mti][tt][1], am[mti][tt][2], am[mti][tt][3],
                             vh[mti].x, vh[mti].y, vh[mti].z, vh[mti].w, bh[tt*2], bh[tt*2+1]);
            // pass 2: hi * Wlo (correction chain)
#pragma unroll
            for (int mti = 0; mti < 2; mti++)
#pragma unroll
                for (int tt = 0; tt < 4; tt++)
                    mma_bf16(ac[mti][tt][0], ac[mti][tt][1], ac[mti][tt][2], ac[mti][tt][3],
                             vh[mti].x, vh[mti].y, vh[mti].z, vh[mti].w, bl[tt*2], bl[tt*2+1]);
            // pass 3: lo * Whi (correction chain)
#pragma unroll
            for (int mti = 0; mti < 2; mti++)
#pragma unroll
                for (int tt = 0; tt < 4; tt++)
                    mma_bf16(ac[mti][tt][0], ac[mti][tt][1], ac[mti][tt][2], ac[mti][tt][3],
                             vl[mti].x, vl[mti].y, vl[mti].z, vl[mti].w, bh[tt*2], bh[tt*2+1]);
        }

        // chain sums into am
#pragma unroll
        for (int mti = 0; mti < 2; mti++)
#pragma unroll
            for (int tt = 0; tt < 4; tt++)
#pragma unroll
                for (int c = 0; c < 4; c++) am[mti][tt][c] += ac[mti][tt][c];

        // write partials for mti's handled by other cell warps
        {
            const int src = (ks < 2) ? 0 : ks - 1;
#pragma unroll
            for (int mti = 0; mti < 2; mti++) {
                if (ks != mti) {
                    int base = ((src * 2 + mtp) * 2 + mti) * 4;
#pragma unroll
                    for (int tt = 0; tt < 4; tt++)
                        red[(base + tt) * 32 + lane] =
                            make_float4(am[mti][tt][0], am[mti][tt][1],
                                        am[mti][tt][2], am[mti][tt][3]);
                }
            }
        }
        __syncthreads();

        float hvv[4];
        if (ks < 2) {
            const int mti = ks;
#pragma unroll
            for (int src = 0; src < 3; src++) {
                int base = ((src * 2 + mtp) * 2 + mti) * 4;
#pragma unroll
                for (int tt = 0; tt < 4; tt++) {
                    float4 v = red[(base + tt) * 32 + lane];
                    am[mti][tt][0] += v.x; am[mti][tt][1] += v.y;
                    am[mti][tt][2] += v.z; am[mti][tt][3] += v.w;
                }
            }
            float (*G)[4] = am[mti];
            float ig, fg, gg, og;
            ig = sigf(G[0][0] + xg0.x); fg = sigf(G[0][1] + xg0.y);
            gg = tanhfast(G[1][0] + xg0.z); og = sigf(G[1][1] + xg0.w);
            cst[0] = fg * cst[0] + ig * gg;  hvv[0] = og * tanhfast(cst[0]);

            ig = sigf(G[0][2] + xg1.x); fg = sigf(G[0][3] + xg1.y);
            gg = tanhfast(G[1][2] + xg1.z); og = sigf(G[1][3] + xg1.w);
            cst[1] = fg * cst[1] + ig * gg;  hvv[1] = og * tanhfast(cst[1]);

            ig = sigf(G[2][0] + xg2.x); fg = sigf(G[2][1] + xg2.y);
            gg = tanhfast(G[3][0] + xg2.z); og = sigf(G[3][1] + xg2.w);
            cst[2] = fg * cst[2] + ig * gg;  hvv[2] = og * tanhfast(cst[2]);

            ig = sigf(G[2][2] + xg3.x); fg = sigf(G[2][3] + xg3.y);
            gg = tanhfast(G[3][2] + xg3.z); og = sigf(G[3][3] + xg3.w);
            cst[3] = fg * cst[3] + ig * gg;  hvv[3] = og * tanhfast(cst[3]);

            // stage packed-h slice
            char* st = smem + SM_STAGE;
            __nv_bfloat16 h0 = __float2bfloat16_rn(hvv[0]);
            __nv_bfloat16 h1 = __float2bfloat16_rn(hvv[1]);
            __nv_bfloat16 h2 = __float2bfloat16_rn(hvv[2]);
            __nv_bfloat16 h3 = __float2bfloat16_rn(hvv[3]);
            *(__nv_bfloat16*)(st + off0)        = h0;
            *(__nv_bfloat16*)(st + off0 + 4)    = h1;
            *(__nv_bfloat16*)(st + off1)        = h2;
            *(__nv_bfloat16*)(st + off1 + 4)    = h3;
            *(__nv_bfloat16*)(st + off0 + 1024) = __float2bfloat16_rn(hvv[0] - __bfloat162float(h0));
            *(__nv_bfloat16*)(st + off0 + 1028) = __float2bfloat16_rn(hvv[1] - __bfloat162float(h1));
            *(__nv_bfloat16*)(st + off1 + 1024) = __float2bfloat16_rn(hvv[2] - __bfloat162float(h2));
            *(__nv_bfloat16*)(st + off1 + 1028) = __float2bfloat16_rn(hvv[3] - __bfloat162float(h3));
        }
        __syncthreads();

        // coalesced packed writeback: 256 threads, one STG.64 each
        {
            const int wbuf = (t + 1) & 1;
            int plane = tid >> 7, rb = (tid >> 5) & 3, lt = tid & 31;
            uint2 v = *(uint2*)(smem + SM_STAGE + (uint32_t)((plane * 4 + rb) * 32 + lt) * 8);
            uint2* dst = (uint2*)&g_hpk[wbuf][plane][rb][kgc][lt];
            dst[blk & 1] = v;
        }

        if (t == T_STEPS - 1) {
            if (ks < 2) {
                out[((size_t)t * BATCH + cb0) * HID + col0] = hvv[0];
                out[((size_t)t * BATCH + cb1) * HID + col0] = hvv[1];
                out[((size_t)t * BATCH + cb0) * HID + col1] = hvv[2];
                out[((size_t)t * BATCH + cb1) * HID + col1] = hvv[3];
                const long long need = (long long)T_STEPS * BATCH * HID + 2LL * BATCH * HID;
                if ((long long)out_size >= need) {
                    size_t base = (size_t)T_STEPS * BATCH * HID;
                    out[base + (size_t)cb0 * HID + col0] = hvv[0];
                    out[base + (size_t)cb1 * HID + col0] = hvv[1];
                    out[base + (size_t)cb0 * HID + col1] = hvv[2];
                    out[base + (size_t)cb1 * HID + col1] = hvv[3];
                    size_t cb = base + (size_t)BATCH * HID;
                    out[cb + (size_t)cb0 * HID + col0] = cst[0];
                    out[cb + (size_t)cb1 * HID + col0] = cst[1];
                    out[cb + (size_t)cb0 * HID + col1] = cst[2];
                    out[cb + (size_t)cb1 * HID + col1] = cst[3];
                }
            }
        } else {
            // writeback STGs -> bar -> release flag (t+1). No global poll; the
            // per-warp waits at the top of the next iteration take over.
            __syncthreads();
            if (tid == 0) st_rel(&g_flags[blk], t + 1);
            if (ks < 2) {
                // out stores + next-step xg prefetch off the critical path
                out[((size_t)t * BATCH + cb0) * HID + col0] = hvv[0];
                out[((size_t)t * BATCH + cb1) * HID + col0] = hvv[1];
                out[((size_t)t * BATCH + cb0) * HID + col1] = hvv[2];
                out[((size_t)t * BATCH + cb1) * HID + col1] = hvv[3];
                const float* xpb = g_xproj + ((size_t)(t + 1) * BATCH) * G4;
                xg0 = *(const float4*)(xpb + (size_t)cb0 * G4 + col0 * 4);
                xg1 = *(const float4*)(xpb + (size_t)cb1 * G4 + col0 * 4);
                xg2 = *(const float4*)(xpb + (size_t)cb0 * G4 + col1 * 4);
                xg3 = *(const float4*)(xpb + (size_t)cb1 * G4 + col1 * 4);
            }
        }
    }
}

// ================= launch =================
extern "C" void kernel_launch(void* const* d_in, const int* in_sizes, int n_in,
                              void* d_out, int out_size) {
    const float* x    = (const float*)d_in[0];
    const float* h0   = (const float*)d_in[1];
    const float* c0   = (const float*)d_in[2];
    const float* w_ih = (const float*)d_in[3];
    const float* w_hh = (const float*)d_in[4];
    const float* b_ih = (const float*)d_in[5];
    const float* b_hh = (const float*)d_in[6];
    float* out = (float*)d_out;

    cudaFuncSetAttribute(xproj_mma,
                         cudaFuncAttributeMaxDynamicSharedMemorySize, XP_SMEM);
    cudaFuncSetAttribute(lstm_rec_pk,
                         cudaFuncAttributeMaxDynamicSharedMemorySize, R_SMEM);

    split_inputs<<<2048, 256>>>(x, w_ih, h0);
    dim3 gx(G4 / 128, (T_STEPS * BATCH) / 128);   // 32 x 512
    xproj_mma<<<gx, 256, XP_SMEM>>>(b_ih, b_hh);
    lstm_rec_pk<<<NBLK, 256, R_SMEM>>>(c0, w_hh, out, out_size);
}

// round 14
// speedup vs baseline: 2.0314x; 1.5053x over previous
#include <cuda_runtime.h>
#include <cuda_bf16.h>
#include <cuda_fp16.h>
#include <math.h>
#include <stdint.h>

#define T_STEPS 1024
#define BATCH   64
#define INDIM   512
#define HID     1024
#define G4      4096

#define NBLK 128

// W-resident smem geometry
#define WROWB   2064                 // 1032 fp16 per W row (1024 + 8 pad)
#define WPLANE  (32 * WROWB)         // 66048
#define SM_W    0
#define SM_STAGE (2 * WPLANE)        // 132096
#define SM_RED  (SM_STAGE + 2048)    // 134144 ; 24KB partial-sum exchange
#define R_SMEM  (SM_RED + 24576)     // 158720

// ---------------- device scratch (static) ----------------
__device__ float          g_xproj[(size_t)T_STEPS * BATCH * G4];   // [t][b][j*4+gate]
__device__ __nv_bfloat16  g_xhi[(size_t)T_STEPS * BATCH * INDIM];
__device__ __nv_bfloat16  g_xlo[(size_t)T_STEPS * BATCH * INDIM];
__device__ __nv_bfloat16  g_wihhi[(size_t)G4 * INDIM];
__device__ __nv_bfloat16  g_wihlo[(size_t)G4 * INDIM];
// h packed fp16 in m16n8k16 A-fragment order: [buf][rb=b>>4][kg=k>>4][lane] = uint4
__device__ uint4          g_hpk[2][4][64][32];
__device__ int            g_flags[NBLK];

// ---------------- helpers ----------------
__device__ __forceinline__ uint32_t smem_u32(const void* p) {
    uint32_t a;
    asm("{ .reg .u64 t; cvta.to.shared.u64 t, %1; cvt.u32.u64 %0, t; }" : "=r"(a) : "l"(p));
    return a;
}

#define LDSM_X4(r0,r1,r2,r3,addr) \
    asm volatile("ldmatrix.sync.aligned.m8n8.x4.shared.b16 {%0,%1,%2,%3}, [%4];" \
                 : "=r"(r0), "=r"(r1), "=r"(r2), "=r"(r3) : "r"(addr))

__device__ __forceinline__ void mma_bf16(float& d0, float& d1, float& d2, float& d3,
                                         uint32_t a0, uint32_t a1, uint32_t a2, uint32_t a3,
                                         uint32_t b0, uint32_t b1) {
    asm volatile(
        "mma.sync.aligned.m16n8k16.row.col.f32.bf16.bf16.f32 "
        "{%0,%1,%2,%3}, {%4,%5,%6,%7}, {%8,%9}, {%0,%1,%2,%3};"
        : "+f"(d0), "+f"(d1), "+f"(d2), "+f"(d3)
        : "r"(a0), "r"(a1), "r"(a2), "r"(a3), "r"(b0), "r"(b1));
}

__device__ __forceinline__ void mma_f16(float& d0, float& d1, float& d2, float& d3,
                                        uint32_t a0, uint32_t a1, uint32_t a2, uint32_t a3,
                                        uint32_t b0, uint32_t b1) {
    asm volatile(
        "mma.sync.aligned.m16n8k16.row.col.f32.f16.f16.f32 "
        "{%0,%1,%2,%3}, {%4,%5,%6,%7}, {%8,%9}, {%0,%1,%2,%3};"
        : "+f"(d0), "+f"(d1), "+f"(d2), "+f"(d3)
        : "r"(a0), "r"(a1), "r"(a2), "r"(a3), "r"(b0), "r"(b1));
}

__device__ __forceinline__ void cp16(uint32_t dst, const void* src) {
    asm volatile("cp.async.cg.shared.global [%0], [%1], 16;" :: "r"(dst), "l"(src) : "memory");
}
#define CP_COMMIT() asm volatile("cp.async.commit_group;" ::: "memory")
#define CP_WAIT(n)  asm volatile("cp.async.wait_group %0;" :: "n"(n) : "memory")

// release/acquire flag ops (no MEMBAR.ALL, no CCTL.IVALL L1 flush)
__device__ __forceinline__ void st_rel(int* p, int v) {
    asm volatile("st.release.gpu.global.s32 [%0], %1;" :: "l"(p), "r"(v) : "memory");
}
__device__ __forceinline__ int ld_acq(const int* p) {
    int v;
    asm volatile("ld.acquire.gpu.global.s32 %0, [%1];" : "=r"(v) : "l"(p) : "memory");
    return v;
}

// fp32x4 -> bf16 hi + bf16 residual (for xproj path)
__device__ __forceinline__ void split4(float4 v, uint2& hip, uint2& lop) {
    __nv_bfloat16 hx = __float2bfloat16_rn(v.x);
    __nv_bfloat16 hy = __float2bfloat16_rn(v.y);
    __nv_bfloat16 hz = __float2bfloat16_rn(v.z);
    __nv_bfloat16 hw = __float2bfloat16_rn(v.w);
    __nv_bfloat162 p0 = __halves2bfloat162(hx, hy);
    __nv_bfloat162 p1 = __halves2bfloat162(hz, hw);
    hip.x = *reinterpret_cast<unsigned*>(&p0);
    hip.y = *reinterpret_cast<unsigned*>(&p1);
    __nv_bfloat162 q0 = __floats2bfloat162_rn(v.x - __bfloat162float(hx),
                                              v.y - __bfloat162float(hy));
    __nv_bfloat162 q1 = __floats2bfloat162_rn(v.z - __bfloat162float(hz),
                                              v.w - __bfloat162float(hw));
    lop.x = *reinterpret_cast<unsigned*>(&q0);
    lop.y = *reinterpret_cast<unsigned*>(&q1);
}

// fp32x4 -> fp16 hi + fp16 residual (for recurrent W path)
__device__ __forceinline__ void split4h(float4 v, uint2& hip, uint2& lop) {
    __half hx = __float2half_rn(v.x);
    __half hy = __float2half_rn(v.y);
    __half hz = __float2half_rn(v.z);
    __half hw = __float2half_rn(v.w);
    __half2 p0 = __halves2half2(hx, hy);
    __half2 p1 = __halves2half2(hz, hw);
    hip.x = *reinterpret_cast<unsigned*>(&p0);
    hip.y = *reinterpret_cast<unsigned*>(&p1);
    __half2 q0 = __floats2half2_rn(v.x - __half2float(hx), v.y - __half2float(hy));
    __half2 q1 = __floats2half2_rn(v.z - __half2float(hz), v.w - __half2float(hw));
    lop.x = *reinterpret_cast<unsigned*>(&q0);
    lop.y = *reinterpret_cast<unsigned*>(&q1);
}

__device__ __forceinline__ float sigf(float x) {
    return __fdividef(1.0f, 1.0f + __expf(-x));
}
__device__ __forceinline__ float tanhfast(float x) {
    return __fdividef(2.0f, 1.0f + __expf(-2.0f * x)) - 1.0f;
}

// ================= split pass =================
__global__ __launch_bounds__(256) void split_inputs(
    const float* __restrict__ x,
    const float* __restrict__ wih,
    const float* __restrict__ h0)
{
    if (blockIdx.x == 0 && threadIdx.x < NBLK) g_flags[threadIdx.x] = 0;

    const size_t NX  = (size_t)T_STEPS * BATCH * INDIM / 4;
    const size_t NW  = (size_t)G4 * INDIM / 4;
    const size_t NH0 = (size_t)BATCH * HID / 4;
    const size_t total = NX + NW + NH0;
    for (size_t i = (size_t)blockIdx.x * blockDim.x + threadIdx.x;
         i < total; i += (size_t)gridDim.x * blockDim.x) {
        if (i < NX) {
            float4 v = ((const float4*)x)[i];
            uint2 h, l; split4(v, h, l);
            ((uint2*)g_xhi)[i] = h;
            ((uint2*)g_xlo)[i] = l;
        } else if (i < NX + NW) {
            size_t k = i - NX;
            float4 v = ((const float4*)wih)[k];
            uint2 h, l; split4(v, h, l);
            ((uint2*)g_wihhi)[k] = h;
            ((uint2*)g_wihlo)[k] = l;
        } else {
            // h0 -> packed fp16 fragment layout, buffer 0
            size_t e4 = i - NX - NW;
            size_t e  = e4 * 4;
            int b = (int)(e >> 10);
            int kbase = (int)(e & 1023);
            float4 v = ((const float4*)h0)[e4];
            float vv[4] = {v.x, v.y, v.z, v.w};
            int r  = b & 15;
            int rb = b >> 4;
#pragma unroll
            for (int q = 0; q < 4; q++) {
                int k  = kbase + q;
                int kg = k >> 4, kk = k & 15;
                int lanep = ((r & 7) << 2) + ((kk & 7) >> 1);
                int reg   = ((kk >= 8) ? 2 : 0) + ((r >= 8) ? 1 : 0);
                int byte_ = kk & 1;
                __half hv = __float2half_rn(vv[q]);
                ((__half*)&g_hpk[0][rb][kg][lanep])[reg * 2 + byte_] = hv;
            }
        }
    }
}

// ================= x_proj GEMM (chain-separated bf16-split HMMA, unchanged R11) ===========
#define XP_ROWB 144
#define XP_TILE (128 * XP_ROWB)
#define XP_BUF  (4 * XP_TILE)
#define XP_SMEM (2 * XP_BUF)

__global__ __launch_bounds__(256) void xproj_mma(
    const float* __restrict__ bih,
    const float* __restrict__ bhh)
{
    extern __shared__ char smem[];
    const uint32_t sb = smem_u32(smem);
    const int tid  = threadIdx.x;
    const int lane = tid & 31;
    const int w    = tid >> 5;
    const int wm   = w & 1;
    const int wn   = w >> 1;
    const int jb   = blockIdx.x * 32;
    const size_t mb = (size_t)blockIdx.y * 128;

    float acc[4][4][4];
#pragma unroll
    for (int a = 0; a < 4; a++)
#pragma unroll
        for (int b = 0; b < 4; b++)
#pragma unroll
            for (int c = 0; c < 4; c++) acc[a][b][c] = 0.f;

    const int a_row = wm * 64 + (lane & 7) + ((lane >> 3) & 1) * 8;
    const int a_k8  = (lane >> 4) * 8;
    const int b_row = wn * 32 + (lane & 7) + (lane >> 4) * 8;
    const int b_k8  = ((lane >> 3) & 1) * 8;

    int st_row[4], st_c[4], st_wrow[4];
#pragma unroll
    for (int q = 0; q < 4; q++) {
        int s = tid * 4 + q;
        st_row[q]  = s >> 3;
        st_c[q]    = s & 7;
        st_wrow[q] = (st_row[q] & 3) * HID + jb + (st_row[q] >> 2);
    }

    auto stage = [&](int kb, int buf) {
        uint32_t base = sb + buf * XP_BUF;
#pragma unroll
        for (int q = 0; q < 4; q++) {
            size_t gk = (size_t)kb * 64 + st_c[q] * 8;
            uint32_t off = st_row[q] * XP_ROWB + st_c[q] * 16;
            cp16(base + 0 * XP_TILE + off, &g_xhi[(mb + st_row[q]) * INDIM + gk]);
            cp16(base + 1 * XP_TILE + off, &g_xlo[(mb + st_row[q]) * INDIM + gk]);
            cp16(base + 2 * XP_TILE + off, &g_wihhi[(size_t)st_wrow[q] * INDIM + gk]);
            cp16(base + 3 * XP_TILE + off, &g_wihlo[(size_t)st_wrow[q] * INDIM + gk]);
        }
        CP_COMMIT();
    };

    stage(0, 0);

    for (int kb = 0; kb < 8; kb++) {
        const int buf = kb & 1;
        if (kb < 7) stage(kb + 1, buf ^ 1);
        if (kb < 7) { CP_WAIT(1); } else { CP_WAIT(0); }
        __syncthreads();

        const uint32_t aHi = sb + buf * XP_BUF;
        const uint32_t aLo = aHi + XP_TILE;
        const uint32_t bHi = aHi + 2 * XP_TILE;
        const uint32_t bLo = aHi + 3 * XP_TILE;

#pragma unroll
        for (int s = 0; s < 4; s++) {
            uint32_t bh[8], bl[8];
#pragma unroll
            for (int p = 0; p < 2; p++) {
                uint32_t off = (b_row + p * 16) * XP_ROWB + (s * 16 + b_k8) * 2;
                LDSM_X4(bh[p*4+0], bh[p*4+1], bh[p*4+2], bh[p*4+3], bHi + off);
                LDSM_X4(bl[p*4+0], bl[p*4+1], bl[p*4+2], bl[p*4+3], bLo + off);
            }
#pragma unroll
            for (int mp = 0; mp < 2; mp++) {
                uint32_t ah[2][4], al[2][4];
#pragma unroll
                for (int mi = 0; mi < 2; mi++) {
                    int mt = mp * 2 + mi;
                    uint32_t off = (a_row + mt * 16) * XP_ROWB + (s * 16 + a_k8) * 2;
                    LDSM_X4(ah[mi][0], ah[mi][1], ah[mi][2], ah[mi][3], aHi + off);
                    LDSM_X4(al[mi][0], al[mi][1], al[mi][2], al[mi][3], aLo + off);
                }
#pragma unroll
                for (int mi = 0; mi < 2; mi++)
#pragma unroll
                    for (int nt = 0; nt < 4; nt++) {
                        float* d = acc[mp * 2 + mi][nt];
                        mma_bf16(d[0], d[1], d[2], d[3],
                                 ah[mi][0], ah[mi][1], ah[mi][2], ah[mi][3],
                                 bh[nt*2], bh[nt*2+1]);
                    }
#pragma unroll
                for (int mi = 0; mi < 2; mi++)
#pragma unroll
                    for (int nt = 0; nt < 4; nt++) {
                        float* d = acc[mp * 2 + mi][nt];
                        mma_bf16(d[0], d[1], d[2], d[3],
                                 ah[mi][0], ah[mi][1], ah[mi][2], ah[mi][3],
                                 bl[nt*2], bl[nt*2+1]);
                    }
#pragma unroll
                for (int mi = 0; mi < 2; mi++)
#pragma unroll
                    for (int nt = 0; nt < 4; nt++) {
                        float* d = acc[mp * 2 + mi][nt];
                        mma_bf16(d[0], d[1], d[2], d[3],
                                 al[mi][0], al[mi][1], al[mi][2], al[mi][3],
                                 bh[nt*2], bh[nt*2+1]);
                    }
            }
        }
        __syncthreads();
    }

    const int colq = (lane & 3) * 2;
#pragma unroll
    for (int nt = 0; nt < 4; nt++) {
        int nloc = wn * 32 + nt * 8 + colq;
        int g0 = nloc & 3,        j0 = jb + (nloc >> 2);
        int g1 = (nloc + 1) & 3,  j1 = jb + ((nloc + 1) >> 2);
        float bb0 = bih[g0 * HID + j0] + bhh[g0 * HID + j0];
        float bb1 = bih[g1 * HID + j1] + bhh[g1 * HID + j1];
#pragma unroll
        for (int mt = 0; mt < 4; mt++) {
            size_t r0 = mb + wm * 64 + mt * 16 + (lane >> 2);
            float2 v0 = make_float2(acc[mt][nt][0] + bb0, acc[mt][nt][1] + bb1);
            float2 v1 = make_float2(acc[mt][nt][2] + bb0, acc[mt][nt][3] + bb1);
            *(float2*)&g_xproj[r0 * G4 + jb * 4 + nloc]       = v0;
            *(float2*)&g_xproj[(r0 + 8) * G4 + jb * 4 + nloc] = v1;
        }
    }
}

// ================= persistent recurrent kernel (fp16 2-term, M2xK4, R11 barrier) ==========
__global__ __launch_bounds__(256, 1) void lstm_rec_pk(
    const float* __restrict__ c0in,
    const float* __restrict__ whh,
    float* __restrict__ out, int out_size)
{
    extern __shared__ char smem[];
    const uint32_t sb = smem_u32(smem);
    const int tid  = threadIdx.x;
    const int lane = tid & 31;
    const int w    = tid >> 5;
    const int mtp  = w & 1;            // m pair
    const int ks   = w >> 1;           // K quarter
    const int blk  = blockIdx.x;
    const int hb   = blk * 8;
    const int kgc  = blk >> 1;

    // one-time: W slice -> smem (gate-interleaved rows, proven mapping), fp16 hi + residual
    for (int it = 0; it < 32; it++) {
        int e4 = it * 256 + tid;
        int n  = e4 >> 8;
        int kf = (e4 & 255) * 4;
        int nh_ = n >> 4, r = n & 15;
        int nt = r >> 3, q = (r & 7) >> 1, low = r & 1;
        int gate = nt * 2 + low, j = 4 * nh_ + q;
        float4 v = *(const float4*)&whh[(size_t)(gate * HID + hb + j) * HID + kf];
        uint2 hp, lp; split4h(v, hp, lp);
        *(uint2*)(smem + SM_W + n * WROWB + kf * 2) = hp;
        *(uint2*)(smem + SM_W + WPLANE + n * WROWB + kf * 2) = lp;
    }
    __syncthreads();

    const uint32_t bRow0 = (uint32_t)((lane & 7) + ((lane >> 4) << 3)) * WROWB;
    const uint32_t bRow1 = bRow0 + 16u * WROWB;
    const uint32_t bK8   = ((lane >> 3) & 1) * 8;

    const int j0 = lane & 3;
    const int j1 = 4 + j0;
    const int col0 = hb + j0;
    const int col1 = hb + j1;

    // cell role: warps ks<2 handle mt = 2*mtp + ks
    const int cmt = 2 * mtp + ks;                 // valid when ks<2
    const int cb0 = cmt * 16 + (lane >> 2);
    const int cb1 = cb0 + 8;
    const uint32_t off0 = (uint32_t)(cmt * 32 + ((lane >> 2) << 2) + (j0 >> 1)) * 8 + (j0 & 1) * 2;
    const uint32_t off1 = (uint32_t)(cmt * 32 + ((lane >> 2) << 2) + (j1 >> 1)) * 8 + (j1 & 1) * 2;

    float cst[4] = {0.f, 0.f, 0.f, 0.f};
    float4 xg0, xg1, xg2, xg3;
    if (ks < 2) {
        cst[0] = c0in[cb0 * HID + col0];
        cst[1] = c0in[cb1 * HID + col0];
        cst[2] = c0in[cb0 * HID + col1];
        cst[3] = c0in[cb1 * HID + col1];
        const float* xpb = g_xproj;
        xg0 = *(const float4*)(xpb + (size_t)cb0 * G4 + col0 * 4);
        xg1 = *(const float4*)(xpb + (size_t)cb1 * G4 + col0 * 4);
        xg2 = *(const float4*)(xpb + (size_t)cb0 * G4 + col1 * 4);
        xg3 = *(const float4*)(xpb + (size_t)cb1 * G4 + col1 * 4);
    }

    float4* red = (float4*)(smem + SM_RED);   // [src(3)][mtp(2)][mti(2)][tt(4)][lane]

    for (int t = 0; t < T_STEPS; t++) {
        const int rbuf = t & 1;
        const uint4* __restrict__ Ahp[2];
#pragma unroll
        for (int mti = 0; mti < 2; mti++)
            Ahp[mti] = &g_hpk[rbuf][2 * mtp + mti][ks * 16][lane];

        // 8-deep A prefetch per m-tile (16 outstanding uint4/thread)
        uint4 pah[8][2];
#pragma unroll
        for (int i = 0; i < 8; i++)
#pragma unroll
            for (int mti = 0; mti < 2; mti++)
                pah[i][mti] = __ldcg(&Ahp[mti][i * 32]);

        float am[2][4][4], ac[2][4][4];
#pragma unroll
        for (int mti = 0; mti < 2; mti++)
#pragma unroll
            for (int tt = 0; tt < 4; tt++)
#pragma unroll
                for (int c = 0; c < 4; c++) { am[mti][tt][c] = 0.f; ac[mti][tt][c] = 0.f; }

#pragma unroll
        for (int kg = 0; kg < 16; kg++) {
            const int slot = kg & 7;
            uint4 vh[2];
#pragma unroll
            for (int mti = 0; mti < 2; mti++) vh[mti] = pah[slot][mti];
            if (kg < 8) {
#pragma unroll
                for (int mti = 0; mti < 2; mti++)
                    pah[slot][mti] = __ldcg(&Ahp[mti][(kg + 8) * 32]);
            }
            const int kgg = ks * 16 + kg;
            const uint32_t ko = (uint32_t)((kgg * 16 + bK8) << 1);
            uint32_t bh[8], bl[8];
            LDSM_X4(bh[0], bh[1], bh[2], bh[3], sb + SM_W + bRow0 + ko);
            LDSM_X4(bh[4], bh[5], bh[6], bh[7], sb + SM_W + bRow1 + ko);
            LDSM_X4(bl[0], bl[1], bl[2], bl[3], sb + SM_W + WPLANE + bRow0 + ko);
            LDSM_X4(bl[4], bl[5], bl[6], bl[7], sb + SM_W + WPLANE + bRow1 + ko);
            // pass 1: h * Whi (main chain)
#pragma unroll
            for (int mti = 0; mti < 2; mti++)
#pragma unroll
                for (int tt = 0; tt < 4; tt++)
                    mma_f16(am[mti][tt][0], am[mti][tt][1], am[mti][tt][2], am[mti][tt][3],
                            vh[mti].x, vh[mti].y, vh[mti].z, vh[mti].w, bh[tt*2], bh[tt*2+1]);
            // pass 2: h * Wlo (correction chain)
#pragma unroll
            for (int mti = 0; mti < 2; mti++)
#pragma unroll
                for (int tt = 0; tt < 4; tt++)
                    mma_f16(ac[mti][tt][0], ac[mti][tt][1], ac[mti][tt][2], ac[mti][tt][3],
                            vh[mti].x, vh[mti].y, vh[mti].z, vh[mti].w, bl[tt*2], bl[tt*2+1]);
        }

        // chain sums into am
#pragma unroll
        for (int mti = 0; mti < 2; mti++)
#pragma unroll
            for (int tt = 0; tt < 4; tt++)
#pragma unroll
                for (int c = 0; c < 4; c++) am[mti][tt][c] += ac[mti][tt][c];

        // write partials for mti's handled by other cell warps
        {
            const int src = (ks < 2) ? 0 : ks - 1;
#pragma unroll
            for (int mti = 0; mti < 2; mti++) {
                if (ks != mti) {
                    int base = ((src * 2 + mtp) * 2 + mti) * 4;
#pragma unroll
                    for (int tt = 0; tt < 4; tt++)
                        red[(base + tt) * 32 + lane] =
                            make_float4(am[mti][tt][0], am[mti][tt][1],
                                        am[mti][tt][2], am[mti][tt][3]);
                }
            }
        }
        __syncthreads();

        float hvv[4];
        if (ks < 2) {
            const int mti = ks;
#pragma unroll
            for (int src = 0; src < 3; src++) {
                int base = ((src * 2 + mtp) * 2 + mti) * 4;
#pragma unroll
                for (int tt = 0; tt < 4; tt++) {
                    float4 v = red[(base + tt) * 32 + lane];
                    am[mti][tt][0] += v.x; am[mti][tt][1] += v.y;
                    am[mti][tt][2] += v.z; am[mti][tt][3] += v.w;
                }
            }
            float (*G)[4] = am[mti];
            float ig, fg, gg, og;
            ig = sigf(G[0][0] + xg0.x); fg = sigf(G[0][1] + xg0.y);
            gg = tanhfast(G[1][0] + xg0.z); og = sigf(G[1][1] + xg0.w);
            cst[0] = fg * cst[0] + ig * gg;  hvv[0] = og * tanhfast(cst[0]);

            ig = sigf(G[0][2] + xg1.x); fg = sigf(G[0][3] + xg1.y);
            gg = tanhfast(G[1][2] + xg1.z); og = sigf(G[1][3] + xg1.w);
            cst[1] = fg * cst[1] + ig * gg;  hvv[1] = og * tanhfast(cst[1]);

            ig = sigf(G[2][0] + xg2.x); fg = sigf(G[2][1] + xg2.y);
            gg = tanhfast(G[3][0] + xg2.z); og = sigf(G[3][1] + xg2.w);
            cst[2] = fg * cst[2] + ig * gg;  hvv[2] = og * tanhfast(cst[2]);

            ig = sigf(G[2][2] + xg3.x); fg = sigf(G[2][3] + xg3.y);
            gg = tanhfast(G[3][2] + xg3.z); og = sigf(G[3][3] + xg3.w);
            cst[3] = fg * cst[3] + ig * gg;  hvv[3] = og * tanhfast(cst[3]);

            // stage packed-h slice (fp16, single plane)
            char* st = smem + SM_STAGE;
            *(__half*)(st + off0)     = __float2half_rn(hvv[0]);
            *(__half*)(st + off0 + 4) = __float2half_rn(hvv[1]);
            *(__half*)(st + off1)     = __float2half_rn(hvv[2]);
            *(__half*)(st + off1 + 4) = __float2half_rn(hvv[3]);
        }
        __syncthreads();

        // coalesced packed writeback: 128 threads, one STG.64 each
        if (tid < 128) {
            const int wbuf = (t + 1) & 1;
            int rb = tid >> 5, lt = tid & 31;
            uint2 v = *(uint2*)(smem + SM_STAGE + (uint32_t)(rb * 32 + lt) * 8);
            uint2* dst = (uint2*)&g_hpk[wbuf][rb][kgc][lt];
            dst[blk & 1] = v;
        }

        if (t == T_STEPS - 1) {
            if (ks < 2) {
                out[((size_t)t * BATCH + cb0) * HID + col0] = hvv[0];
                out[((size_t)t * BATCH + cb1) * HID + col0] = hvv[1];
                out[((size_t)t * BATCH + cb0) * HID + col1] = hvv[2];
                out[((size_t)t * BATCH + cb1) * HID + col1] = hvv[3];
                const long long need = (long long)T_STEPS * BATCH * HID + 2LL * BATCH * HID;
                if ((long long)out_size >= need) {
                    size_t base = (size_t)T_STEPS * BATCH * HID;
                    out[base + (size_t)cb0 * HID + col0] = hvv[0];
                    out[base + (size_t)cb1 * HID + col0] = hvv[1];
                    out[base + (size_t)cb0 * HID + col1] = hvv[2];
                    out[base + (size_t)cb1 * HID + col1] = hvv[3];
                    size_t cb = base + (size_t)BATCH * HID;
                    out[cb + (size_t)cb0 * HID + col0] = cst[0];
                    out[cb + (size_t)cb1 * HID + col0] = cst[1];
                    out[cb + (size_t)cb0 * HID + col1] = cst[2];
                    out[cb + (size_t)cb1 * HID + col1] = cst[3];
                }
            }
        } else {
            // writeback STGs -> bar -> release flag; tid<128 acquire-poll; bar.
            __syncthreads();
            if (tid == 0) st_rel(&g_flags[blk], t + 1);
            if (ks < 2) {
                // out stores + next-step xg prefetch off the critical path
                out[((size_t)t * BATCH + cb0) * HID + col0] = hvv[0];
                out[((size_t)t * BATCH + cb1) * HID + col0] = hvv[1];
                out[((size_t)t * BATCH + cb0) * HID + col1] = hvv[2];
                out[((size_t)t * BATCH + cb1) * HID + col1] = hvv[3];
                const float* xpb = g_xproj + ((size_t)(t + 1) * BATCH) * G4;
                xg0 = *(const float4*)(xpb + (size_t)cb0 * G4 + col0 * 4);
                xg1 = *(const float4*)(xpb + (size_t)cb1 * G4 + col0 * 4);
                xg2 = *(const float4*)(xpb + (size_t)cb0 * G4 + col1 * 4);
                xg3 = *(const float4*)(xpb + (size_t)cb1 * G4 + col1 * 4);
            }
            if (tid < NBLK) {
                while (ld_acq(&g_flags[tid]) < t + 1) { __nanosleep(32); }
            }
            __syncthreads();
        }
    }
}

// ================= launch =================
extern "C" void kernel_launch(void* const* d_in, const int* in_sizes, int n_in,
                              void* d_out, int out_size) {
    const float* x    = (const float*)d_in[0];
    const float* h0   = (const float*)d_in[1];
    const float* c0   = (const float*)d_in[2];
    const float* w_ih = (const float*)d_in[3];
    const float* w_hh = (const float*)d_in[4];
    const float* b_ih = (const float*)d_in[5];
    const float* b_hh = (const float*)d_in[6];
    float* out = (float*)d_out;

    cudaFuncSetAttribute(xproj_mma,
                         cudaFuncAttributeMaxDynamicSharedMemorySize, XP_SMEM);
    cudaFuncSetAttribute(lstm_rec_pk,
                         cudaFuncAttributeMaxDynamicSharedMemorySize, R_SMEM);

    split_inputs<<<2048, 256>>>(x, w_ih, h0);
    dim3 gx(G4 / 128, (T_STEPS * BATCH) / 128);   // 32 x 512
    xproj_mma<<<gx, 256, XP_SMEM>>>(b_ih, b_hh);
    lstm_rec_pk<<<NBLK, 256, R_SMEM>>>(c0, w_hh, out, out_size);
}